// round 4
// baseline (speedup 1.0000x reference)
#include <cuda_runtime.h>

#define THREADS 256
#define BM 128          // tokens per block
#define BN 64           // codes per tile
#define BK 64           // d-chunk for codebook staging
#define D_DIM 256
#define ASTRIDE 260     // 260 mod 32 = 4 -> ty-adjacent rows in different banks
#define BSTRIDE 65      // B reads at most 2-way conflicted

__device__ float g_csq[4096];   // ||c_k||^2, K <= 4096

// ---------------------------------------------------------------------------
// csq: one warp per codebook row
// ---------------------------------------------------------------------------
__global__ void csq_kernel(const float* __restrict__ cb, int K) {
    int k = blockIdx.x * (blockDim.x / 32) + (threadIdx.x >> 5);
    int lane = threadIdx.x & 31;
    if (k >= K) return;
    const float* row = cb + (size_t)k * D_DIM;
    float s = 0.f;
    #pragma unroll
    for (int d = lane; d < D_DIM; d += 32) {
        float v = row[d];
        s = fmaf(v, v, s);
    }
    #pragma unroll
    for (int o = 16; o; o >>= 1) s += __shfl_xor_sync(0xffffffffu, s, o);
    if (lane == 0) g_csq[k] = s;
}

// ---------------------------------------------------------------------------
// Fused GEMM + argmin + gather.
// 256 threads as (tx=16 code-cols) x (ty=16 row-groups).
// Micro-tile per thread: 8 rows (row = ty + 16*i) x 4 cols (col = tx*4+j).
// smem: As (z tile) | Bs (codebook chunk). After the main loop As is dead,
// so the argmin reduction buffers alias its storage.
// ---------------------------------------------------------------------------
__global__ __launch_bounds__(THREADS, 1)
void vq_kernel(const float* __restrict__ z, const float* __restrict__ cb,
               float* __restrict__ zq, float* __restrict__ idx_out,
               int K, int write_idx) {
    extern __shared__ float smem[];
    float* As   = smem;                        // BM * ASTRIDE floats
    float* Bs   = As + BM * ASTRIDE;           // BN * BSTRIDE floats
    float* redD = As;                          // aliases As (dead after loop)
    int*   redI = (int*)(As + BM * 16);        // BM * 16 ints, after redD
    __shared__ int rowIdx[BM];

    const int tid = threadIdx.x;
    const int tx  = tid & 15;
    const int ty  = tid >> 4;
    const long m0 = (long)blockIdx.x * BM;

    // ---- load z tile (128 x 256, contiguous in gmem) ----
    const float4* zsrc = (const float4*)(z + m0 * D_DIM);
    for (int f = tid; f < BM * (D_DIM / 4); f += THREADS) {
        float4 v = zsrc[f];
        int row = f >> 6;           // 64 float4 per row
        int c4  = f & 63;
        *(float4*)&As[row * ASTRIDE + c4 * 4] = v;
    }
    __syncthreads();

    float bestD[8];
    int   bestI[8];
    #pragma unroll
    for (int i = 0; i < 8; i++) { bestD[i] = 3.4e38f; bestI[i] = 0; }

    const int col0t = tx * 4;
    const float* Abase = &As[ty * ASTRIDE];    // micro-row i at +i*16*ASTRIDE

    for (int nt = 0; nt < K / BN; ++nt) {
        const int n0 = nt * BN;
        float acc[8][4];
        #pragma unroll
        for (int i = 0; i < 8; i++)
            #pragma unroll
            for (int j = 0; j < 4; j++) acc[i][j] = 0.f;

        #pragma unroll
        for (int dc = 0; dc < D_DIM / BK; ++dc) {
            // stage codebook chunk (64 codes x 64 dims)
            for (int f = tid; f < BN * (BK / 4); f += THREADS) {
                int r = f >> 4, c4 = f & 15;
                float4 v = __ldg((const float4*)(cb + (size_t)(n0 + r) * D_DIM
                                                 + dc * BK + c4 * 4));
                float* dst = &Bs[r * BSTRIDE + c4 * 4];
                dst[0] = v.x; dst[1] = v.y; dst[2] = v.z; dst[3] = v.w;
            }
            __syncthreads();

            const float* Ap = Abase + dc * BK;
            const float* Bp = &Bs[col0t * BSTRIDE];
            #pragma unroll 8
            for (int d = 0; d < BK; ++d) {
                float b0 = Bp[d];
                float b1 = Bp[BSTRIDE + d];
                float b2 = Bp[2 * BSTRIDE + d];
                float b3 = Bp[3 * BSTRIDE + d];
                #pragma unroll
                for (int i = 0; i < 8; ++i) {
                    float a = Ap[i * (16 * ASTRIDE) + d];
                    acc[i][0] = fmaf(a, b0, acc[i][0]);
                    acc[i][1] = fmaf(a, b1, acc[i][1]);
                    acc[i][2] = fmaf(a, b2, acc[i][2]);
                    acc[i][3] = fmaf(a, b3, acc[i][3]);
                }
            }
            __syncthreads();
        }

        // fused argmin update: dist = ||c||^2 - 2 z.c  (||z||^2 is row-constant)
        #pragma unroll
        for (int j = 0; j < 4; j++) {
            int col = n0 + col0t + j;
            float cs = g_csq[col];
            #pragma unroll
            for (int i = 0; i < 8; i++) {
                float dist = fmaf(-2.f, acc[i][j], cs);
                if (dist < bestD[i]) { bestD[i] = dist; bestI[i] = col; }
            }
        }
    }

    __syncthreads();   // As reads done; safe to overwrite with redD/redI

    // ---- cross-thread argmin per row (16 tx threads share each row) ----
    #pragma unroll
    for (int i = 0; i < 8; i++) {
        int row = ty + 16 * i;
        redD[row * 16 + tx] = bestD[i];
        redI[row * 16 + tx] = bestI[i];
    }
    __syncthreads();
    if (tid < BM) {
        float bd = redD[tid * 16];
        int   bi = redI[tid * 16];
        #pragma unroll
        for (int t = 1; t < 16; t++) {
            float d = redD[tid * 16 + t];
            int  ii = redI[tid * 16 + t];
            if (d < bd || (d == bd && ii < bi)) { bd = d; bi = ii; }
        }
        rowIdx[tid] = bi;
        if (write_idx) idx_out[m0 + tid] = (float)bi;
    }
    __syncthreads();

    // ---- gather z_q = codebook[idx] (coalesced float4) ----
    float4* zqdst = (float4*)(zq + m0 * D_DIM);
    for (int f = tid; f < BM * (D_DIM / 4); f += THREADS) {
        int row = f >> 6;
        int c4  = f & 63;
        float4 v = __ldg((const float4*)(cb + (size_t)rowIdx[row] * D_DIM + c4 * 4));
        zqdst[f] = v;
    }
}

// ---------------------------------------------------------------------------
extern "C" void kernel_launch(void* const* d_in, const int* in_sizes, int n_in,
                              void* d_out, int out_size) {
    const float* z  = (const float*)d_in[0];
    const float* cb = (const float*)d_in[1];
    const int zElems  = in_sizes[0];
    const int cbElems = in_sizes[1];
    const int ntok = zElems / D_DIM;
    const int K    = cbElems / D_DIM;

    float* out     = (float*)d_out;
    float* idx_out = out + (size_t)zElems;
    // tuple output flattened as (z_q, indices); only write indices if the
    // output buffer actually has room for them.
    const int write_idx = (out_size >= zElems + ntok) ? 1 : 0;

    csq_kernel<<<(K + 7) / 8, 256>>>(cb, K);

    const int smemBytes = (BM * ASTRIDE + BN * BSTRIDE) * (int)sizeof(float);
    cudaFuncSetAttribute(vq_kernel,
                         cudaFuncAttributeMaxDynamicSharedMemorySize, smemBytes);
    vq_kernel<<<ntok / BM, THREADS, smemBytes>>>(z, cb, out, idx_out, K, write_idx);
}

// round 5
// speedup vs baseline: 1.9372x; 1.9372x over previous
#include <cuda_runtime.h>

#define THREADS 256
#define BM 64           // tokens per block
#define BN 64           // codes per tile
#define BK 64           // d-chunk
#define D_DIM 256
#define ASTRIDE 260     // mult of 4 (aligned float4 over d); bank spread ok
#define BSTRIDE 65      // B scalar loads: bank=(4tx+j+d)%32 -> conflict-free

__device__ float g_csq[4096];   // ||c_k||^2, K <= 4096

// ---------------------------------------------------------------------------
__global__ void csq_kernel(const float* __restrict__ cb, int K) {
    int k = blockIdx.x * (blockDim.x / 32) + (threadIdx.x >> 5);
    int lane = threadIdx.x & 31;
    if (k >= K) return;
    const float* row = cb + (size_t)k * D_DIM;
    float s = 0.f;
    #pragma unroll
    for (int d = lane; d < D_DIM; d += 32) {
        float v = row[d];
        s = fmaf(v, v, s);
    }
    #pragma unroll
    for (int o = 16; o; o >>= 1) s += __shfl_xor_sync(0xffffffffu, s, o);
    if (lane == 0) g_csq[k] = s;
}

// ---------------------------------------------------------------------------
// Fused GEMM + argmin + gather. 256 threads = (tx 16 cols) x (ty 16 rowgrps),
// 4x4 micro-tile. 2 CTAs/SM. B double-buffered with LDG prefetch, 1 sync/chunk.
// ---------------------------------------------------------------------------
__global__ __launch_bounds__(THREADS, 2)
void vq_kernel(const float* __restrict__ z, const float* __restrict__ cb,
               float* __restrict__ zq, float* __restrict__ idx_out,
               int K, int write_idx) {
    extern __shared__ float smem[];
    float* As  = smem;                         // BM * ASTRIDE
    float* Bs0 = As + BM * ASTRIDE;            // BN * BSTRIDE
    float* Bs1 = Bs0 + BN * BSTRIDE;           // BN * BSTRIDE
    float* redD = As;                          // aliases As (dead after loop)
    int*   redI = (int*)(As + BM * 16);
    __shared__ int rowIdx[BM];

    const int tid = threadIdx.x;
    const int tx  = tid & 15;
    const int ty  = tid >> 4;
    const long m0 = (long)blockIdx.x * BM;

    const int NCHUNK = (K / BN) * (D_DIM / BK);   // 64 for K=1024

    // ---- load z tile (64 x 256 contiguous) ----
    const float4* zsrc = (const float4*)(z + m0 * D_DIM);
    #pragma unroll 4
    for (int f = tid; f < BM * (D_DIM / 4); f += THREADS) {
        float4 v = zsrc[f];
        *(float4*)&As[(f >> 6) * ASTRIDE + (f & 63) * 4] = v;
    }

    // ---- chunk loader: ck -> (n0, dcol); each thread 4 float4 ----
    // f = tid + t*256 : r = f>>4 (code row), c4 = f&15 (float4 within 64 d's)
    float4 pf[4];
    {   // prefetch chunk 0
        const float* src = cb;   // n0=0, dcol=0
        #pragma unroll
        for (int t = 0; t < 4; t++) {
            int f = tid + t * THREADS;
            pf[t] = __ldg((const float4*)(src + (size_t)(f >> 4) * D_DIM + (f & 15) * 4));
        }
        #pragma unroll
        for (int t = 0; t < 4; t++) {
            int f = tid + t * THREADS;
            float* dst = &Bs0[(f >> 4) * BSTRIDE + (f & 15) * 4];
            dst[0] = pf[t].x; dst[1] = pf[t].y; dst[2] = pf[t].z; dst[3] = pf[t].w;
        }
    }
    __syncthreads();   // As + Bs0 ready

    float bestD[4];
    int   bestI[4];
    #pragma unroll
    for (int i = 0; i < 4; i++) { bestD[i] = 3.4e38f; bestI[i] = 0; }

    float acc[4][4];
    const float* ArowBase = As + (ty * 4) * ASTRIDE;

    for (int ck = 0; ck < NCHUNK; ++ck) {
        if ((ck & 3) == 0) {
            #pragma unroll
            for (int i = 0; i < 4; i++)
                #pragma unroll
                for (int j = 0; j < 4; j++) acc[i][j] = 0.f;
        }

        // issue prefetch of next chunk (overlaps with compute below)
        if (ck + 1 < NCHUNK) {
            int nck = ck + 1;
            const float* src = cb + (size_t)((nck >> 2) * BN) * D_DIM + (nck & 3) * BK;
            #pragma unroll
            for (int t = 0; t < 4; t++) {
                int f = tid + t * THREADS;
                pf[t] = __ldg((const float4*)(src + (size_t)(f >> 4) * D_DIM + (f & 15) * 4));
            }
        }

        const float* Bs_cur = (ck & 1) ? Bs1 : Bs0;
        const float* Ap = ArowBase + (ck & 3) * BK;
        const float* Bp = Bs_cur + (tx * 4) * BSTRIDE;

        #pragma unroll 8
        for (int d = 0; d < BK; d += 4) {
            float4 a0 = *(const float4*)(Ap + d);
            float4 a1 = *(const float4*)(Ap + ASTRIDE + d);
            float4 a2 = *(const float4*)(Ap + 2 * ASTRIDE + d);
            float4 a3 = *(const float4*)(Ap + 3 * ASTRIDE + d);
            #pragma unroll
            for (int j = 0; j < 4; j++) {
                const float* bj = Bp + j * BSTRIDE + d;
                float b0 = bj[0], b1 = bj[1], b2 = bj[2], b3 = bj[3];
                acc[0][j] = fmaf(a0.x, b0, acc[0][j]);
                acc[1][j] = fmaf(a1.x, b0, acc[1][j]);
                acc[2][j] = fmaf(a2.x, b0, acc[2][j]);
                acc[3][j] = fmaf(a3.x, b0, acc[3][j]);
                acc[0][j] = fmaf(a0.y, b1, acc[0][j]);
                acc[1][j] = fmaf(a1.y, b1, acc[1][j]);
                acc[2][j] = fmaf(a2.y, b1, acc[2][j]);
                acc[3][j] = fmaf(a3.y, b1, acc[3][j]);
                acc[0][j] = fmaf(a0.z, b2, acc[0][j]);
                acc[1][j] = fmaf(a1.z, b2, acc[1][j]);
                acc[2][j] = fmaf(a2.z, b2, acc[2][j]);
                acc[3][j] = fmaf(a3.z, b2, acc[3][j]);
                acc[0][j] = fmaf(a0.w, b3, acc[0][j]);
                acc[1][j] = fmaf(a1.w, b3, acc[1][j]);
                acc[2][j] = fmaf(a2.w, b3, acc[2][j]);
                acc[3][j] = fmaf(a3.w, b3, acc[3][j]);
            }
        }

        // store prefetched chunk into alternate buffer; single sync per chunk
        if (ck + 1 < NCHUNK) {
            float* Bs_nxt = (ck & 1) ? Bs0 : Bs1;
            #pragma unroll
            for (int t = 0; t < 4; t++) {
                int f = tid + t * THREADS;
                float* dst = &Bs_nxt[(f >> 4) * BSTRIDE + (f & 15) * 4];
                dst[0] = pf[t].x; dst[1] = pf[t].y; dst[2] = pf[t].z; dst[3] = pf[t].w;
            }
            __syncthreads();
        }

        // argmin at tile boundary: dist = ||c||^2 - 2 z.c
        if ((ck & 3) == 3) {
            int n0 = (ck >> 2) * BN;
            #pragma unroll
            for (int j = 0; j < 4; j++) {
                int col = n0 + tx * 4 + j;
                float cs = g_csq[col];
                #pragma unroll
                for (int i = 0; i < 4; i++) {
                    float dist = fmaf(-2.f, acc[i][j], cs);
                    if (dist < bestD[i]) { bestD[i] = dist; bestI[i] = col; }
                }
            }
        }
    }

    __syncthreads();   // As reads done; safe to alias with redD/redI

    // ---- cross-thread argmin per row ----
    #pragma unroll
    for (int i = 0; i < 4; i++) {
        int row = ty * 4 + i;
        redD[row * 16 + tx] = bestD[i];
        redI[row * 16 + tx] = bestI[i];
    }
    __syncthreads();
    if (tid < BM) {
        float bd = redD[tid * 16];
        int   bi = redI[tid * 16];
        #pragma unroll
        for (int t = 1; t < 16; t++) {
            float d = redD[tid * 16 + t];
            int  ii = redI[tid * 16 + t];
            if (d < bd || (d == bd && ii < bi)) { bd = d; bi = ii; }
        }
        rowIdx[tid] = bi;
        if (write_idx) idx_out[m0 + tid] = (float)bi;
    }
    __syncthreads();

    // ---- gather z_q = codebook[idx] (coalesced float4) ----
    float4* zqdst = (float4*)(zq + m0 * D_DIM);
    #pragma unroll 4
    for (int f = tid; f < BM * (D_DIM / 4); f += THREADS) {
        float4 v = __ldg((const float4*)(cb + (size_t)rowIdx[f >> 6] * D_DIM + (f & 63) * 4));
        zqdst[f] = v;
    }
}

// ---------------------------------------------------------------------------
extern "C" void kernel_launch(void* const* d_in, const int* in_sizes, int n_in,
                              void* d_out, int out_size) {
    const float* z  = (const float*)d_in[0];
    const float* cb = (const float*)d_in[1];
    const int zElems  = in_sizes[0];
    const int cbElems = in_sizes[1];
    const int ntok = zElems / D_DIM;
    const int K    = cbElems / D_DIM;

    float* out     = (float*)d_out;
    float* idx_out = out + (size_t)zElems;
    const int write_idx = (out_size >= zElems + ntok) ? 1 : 0;

    csq_kernel<<<(K + 7) / 8, 256>>>(cb, K);

    const int smemBytes = (BM * ASTRIDE + 2 * BN * BSTRIDE) * (int)sizeof(float);
    cudaFuncSetAttribute(vq_kernel,
                         cudaFuncAttributeMaxDynamicSharedMemorySize, smemBytes);
    vq_kernel<<<ntok / BM, THREADS, smemBytes>>>(z, cb, out, idx_out, K, write_idx);
}

// round 6
// speedup vs baseline: 1.9540x; 1.0087x over previous
#include <cuda_runtime.h>

#define THREADS 256
#define BM 128          // tokens per block
#define BN 128          // codes per tile
#define BK 64           // d-chunk
#define D_DIM 256

__device__ float g_csq[4096];   // ||c_k||^2, K <= 4096

// swizzled float-offset within a transposed row of 128 floats:
// row d, logical element e (0..127) -> ((e/4) ^ (d&31))*4 + e%4
__device__ __forceinline__ int swz(int e, int d) {
    return (((e >> 2) ^ (d & 31)) << 2) | (e & 3);
}

// ---------------------------------------------------------------------------
__global__ void csq_kernel(const float* __restrict__ cb, int K) {
    int k = blockIdx.x * (blockDim.x / 32) + (threadIdx.x >> 5);
    int lane = threadIdx.x & 31;
    if (k >= K) return;
    const float* row = cb + (size_t)k * D_DIM;
    float s = 0.f;
    #pragma unroll
    for (int d = lane; d < D_DIM; d += 32) {
        float v = row[d];
        s = fmaf(v, v, s);
    }
    #pragma unroll
    for (int o = 16; o; o >>= 1) s += __shfl_xor_sync(0xffffffffu, s, o);
    if (lane == 0) g_csq[k] = s;
}

// ---------------------------------------------------------------------------
// Fused GEMM + argmin + gather. 256 threads = (tx 16) x (ty 16), 8x8 micro-
// tile per thread (rows ty*4+{0..3}, 64+ty*4+{0..3}; cols same with tx).
// As/Bs stored d-major (transposed) with XOR swizzle; B double-buffered.
// ---------------------------------------------------------------------------
__global__ __launch_bounds__(THREADS, 1)
void vq_kernel(const float* __restrict__ z, const float* __restrict__ cb,
               float* __restrict__ zq, float* __restrict__ idx_out,
               int K, int write_idx) {
    extern __shared__ float smem[];
    float* As  = smem;                   // [D_DIM][BM] swizzled  (128 KB)
    float* Bs0 = As + D_DIM * BM;        // [BK][BN]  swizzled
    float* Bs1 = Bs0 + BK * BN;          // [BK][BN]
    float* redD = As;                    // aliases As (dead after main loop)
    int*   redI = (int*)(As + BM * 16);
    __shared__ int rowIdx[BM];

    const int tid = threadIdx.x;
    const int tx  = tid & 15;
    const int ty  = tid >> 4;
    const long m0 = (long)blockIdx.x * BM;

    const int NCHUNK = (K / BN) * (D_DIM / BK);   // 32 for K=1024

    // ---- stage z tile transposed: As[d][m] = z[m0+m][d] ----
    const float4* zsrc = (const float4*)(z + m0 * D_DIM);
    #pragma unroll 4
    for (int f = tid; f < BM * (D_DIM / 4); f += THREADS) {
        int m = f >> 6, d0 = (f & 63) * 4;
        float4 v = zsrc[f];
        As[(d0 + 0) * BM + swz(m, d0 + 0)] = v.x;
        As[(d0 + 1) * BM + swz(m, d0 + 1)] = v.y;
        As[(d0 + 2) * BM + swz(m, d0 + 2)] = v.z;
        As[(d0 + 3) * BM + swz(m, d0 + 3)] = v.w;
    }

    // ---- prefetch + stage B chunk 0 (codes 0..127, d 0..63) ----
    float4 pf[8];
    #pragma unroll
    for (int t = 0; t < 8; t++) {
        int f = tid + t * THREADS;            // r = f>>4 (code), c4 = f&15
        pf[t] = __ldg((const float4*)(cb + (size_t)(f >> 4) * D_DIM + (f & 15) * 4));
    }
    #pragma unroll
    for (int t = 0; t < 8; t++) {
        int f = tid + t * THREADS;
        int r = f >> 4, d0 = (f & 15) * 4;
        Bs0[(d0 + 0) * BN + swz(r, d0 + 0)] = pf[t].x;
        Bs0[(d0 + 1) * BN + swz(r, d0 + 1)] = pf[t].y;
        Bs0[(d0 + 2) * BN + swz(r, d0 + 2)] = pf[t].z;
        Bs0[(d0 + 3) * BN + swz(r, d0 + 3)] = pf[t].w;
    }
    __syncthreads();

    float bestD[8];
    int   bestI[8];
    #pragma unroll
    for (int i = 0; i < 8; i++) { bestD[i] = 3.4e38f; bestI[i] = 0; }

    float acc[8][8];

    for (int ck = 0; ck < NCHUNK; ++ck) {
        if ((ck & 3) == 0) {
            #pragma unroll
            for (int i = 0; i < 8; i++)
                #pragma unroll
                for (int j = 0; j < 8; j++) acc[i][j] = 0.f;
        }

        // issue LDG prefetch of next chunk (overlaps compute)
        if (ck + 1 < NCHUNK) {
            int nck = ck + 1;
            const float* src = cb + (size_t)((nck >> 2) * BN) * D_DIM + (nck & 3) * BK;
            #pragma unroll
            for (int t = 0; t < 8; t++) {
                int f = tid + t * THREADS;
                pf[t] = __ldg((const float4*)(src + (size_t)(f >> 4) * D_DIM + (f & 15) * 4));
            }
        }

        const float* Bsc = (ck & 1) ? Bs1 : Bs0;
        const float* Asc = As + ((ck & 3) * BK) * BM;   // global-d base; (gd&31)==(d&31)

        #pragma unroll 32
        for (int d = 0; d < BK; ++d) {
            const float* AsD = Asc + d * BM;
            const float* BsD = Bsc + d * BN;
            // swizzled chunk indices: compile-time (d&31) after unroll-32
            float4 a0 = *(const float4*)(AsD + (((ty      ) ^ (d & 31)) << 2));
            float4 a1 = *(const float4*)(AsD + (((ty + 16) ^ (d & 31)) << 2));
            float4 b0 = *(const float4*)(BsD + (((tx      ) ^ (d & 31)) << 2));
            float4 b1 = *(const float4*)(BsD + (((tx + 16) ^ (d & 31)) << 2));
            float av[8] = {a0.x, a0.y, a0.z, a0.w, a1.x, a1.y, a1.z, a1.w};
            float bv[8] = {b0.x, b0.y, b0.z, b0.w, b1.x, b1.y, b1.z, b1.w};
            #pragma unroll
            for (int i = 0; i < 8; i++)
                #pragma unroll
                for (int j = 0; j < 8; j++)
                    acc[i][j] = fmaf(av[i], bv[j], acc[i][j]);
        }

        // stage prefetched chunk into alternate buffer; one sync per chunk
        if (ck + 1 < NCHUNK) {
            float* Bsn = (ck & 1) ? Bs0 : Bs1;
            #pragma unroll
            for (int t = 0; t < 8; t++) {
                int f = tid + t * THREADS;
                int r = f >> 4, d0 = (f & 15) * 4;
                Bsn[(d0 + 0) * BN + swz(r, d0 + 0)] = pf[t].x;
                Bsn[(d0 + 1) * BN + swz(r, d0 + 1)] = pf[t].y;
                Bsn[(d0 + 2) * BN + swz(r, d0 + 2)] = pf[t].z;
                Bsn[(d0 + 3) * BN + swz(r, d0 + 3)] = pf[t].w;
            }
            __syncthreads();
        }

        // argmin at code-tile boundary: dist = ||c||^2 - 2 z.c
        if ((ck & 3) == 3) {
            int n0 = (ck >> 2) * BN;
            #pragma unroll
            for (int j = 0; j < 8; j++) {
                int col = n0 + ((j < 4) ? (tx * 4 + j) : (64 + tx * 4 + j - 4));
                float cs = g_csq[col];
                #pragma unroll
                for (int i = 0; i < 8; i++) {
                    float dist = fmaf(-2.f, acc[i][j], cs);
                    if (dist < bestD[i]) { bestD[i] = dist; bestI[i] = col; }
                }
            }
        }
    }

    __syncthreads();   // main-loop reads of As done; safe to alias redD/redI

    // ---- cross-thread argmin per row (16 tx threads share each row) ----
    #pragma unroll
    for (int i = 0; i < 8; i++) {
        int row = (i < 4) ? (ty * 4 + i) : (64 + ty * 4 + i - 4);
        redD[row * 16 + tx] = bestD[i];
        redI[row * 16 + tx] = bestI[i];
    }
    __syncthreads();
    if (tid < BM) {
        float bd = redD[tid * 16];
        int   bi = redI[tid * 16];
        #pragma unroll
        for (int t = 1; t < 16; t++) {
            float d = redD[tid * 16 + t];
            int  ii = redI[tid * 16 + t];
            if (d < bd || (d == bd && ii < bi)) { bd = d; bi = ii; }
        }
        rowIdx[tid] = bi;
        if (write_idx) idx_out[m0 + tid] = (float)bi;
    }
    __syncthreads();

    // ---- gather z_q = codebook[idx] (coalesced float4) ----
    float4* zqdst = (float4*)(zq + m0 * D_DIM);
    #pragma unroll 4
    for (int f = tid; f < BM * (D_DIM / 4); f += THREADS) {
        float4 v = __ldg((const float4*)(cb + (size_t)rowIdx[f >> 6] * D_DIM + (f & 63) * 4));
        zqdst[f] = v;
    }
}

// ---------------------------------------------------------------------------
extern "C" void kernel_launch(void* const* d_in, const int* in_sizes, int n_in,
                              void* d_out, int out_size) {
    const float* z  = (const float*)d_in[0];
    const float* cb = (const float*)d_in[1];
    const int zElems  = in_sizes[0];
    const int cbElems = in_sizes[1];
    const int ntok = zElems / D_DIM;
    const int K    = cbElems / D_DIM;

    float* out     = (float*)d_out;
    float* idx_out = out + (size_t)zElems;
    const int write_idx = (out_size >= zElems + ntok) ? 1 : 0;

    csq_kernel<<<(K + 7) / 8, 256>>>(cb, K);

    const int smemBytes = (D_DIM * BM + 2 * BK * BN) * (int)sizeof(float);
    cudaFuncSetAttribute(vq_kernel,
                         cudaFuncAttributeMaxDynamicSharedMemorySize, smemBytes);
    vq_kernel<<<ntok / BM, THREADS, smemBytes>>>(z, cb, out, idx_out, K, write_idx);
}

// round 8
// speedup vs baseline: 2.1432x; 1.0968x over previous
#include <cuda_runtime.h>

#define THREADS 256
#define BM 128          // tokens per block
#define BN 128          // codes per tile
#define BK 64           // d-chunk
#define D_DIM 256

__device__ float g_csq[4096];   // ||c_k||^2, K <= 4096

// swizzled float-offset within a transposed row of 128 floats:
// row d, logical element e (0..127) -> ((e/4) ^ (d&31))*4 + e%4
__device__ __forceinline__ int swz(int e, int d) {
    return (((e >> 2) ^ (d & 31)) << 2) | (e & 3);
}

// ---- packed f32x2 helpers (FFMA2: one issue slot, two fp32 FMA lanes) ----
__device__ __forceinline__ unsigned long long pack2(float x, float y) {
    unsigned long long r;
    asm("mov.b64 %0, {%1, %2};" : "=l"(r) : "f"(x), "f"(y));
    return r;
}
__device__ __forceinline__ void fma2(unsigned long long& d,
                                     unsigned long long a, unsigned long long b) {
    asm("fma.rn.f32x2 %0, %1, %2, %0;" : "+l"(d) : "l"(a), "l"(b));
}
__device__ __forceinline__ void unpack2(unsigned long long v, float& lo, float& hi) {
    asm("mov.b64 {%0, %1}, %2;" : "=f"(lo), "=f"(hi) : "l"(v));
}

// ---------------------------------------------------------------------------
__global__ void csq_kernel(const float* __restrict__ cb, int K) {
    int k = blockIdx.x * (blockDim.x / 32) + (threadIdx.x >> 5);
    int lane = threadIdx.x & 31;
    if (k >= K) return;
    const float* row = cb + (size_t)k * D_DIM;
    float s = 0.f;
    #pragma unroll
    for (int d = lane; d < D_DIM; d += 32) {
        float v = row[d];
        s = fmaf(v, v, s);
    }
    #pragma unroll
    for (int o = 16; o; o >>= 1) s += __shfl_xor_sync(0xffffffffu, s, o);
    if (lane == 0) g_csq[k] = s;
}

// ---------------------------------------------------------------------------
// Fused GEMM + argmin + gather. 256 threads = (tx 16) x (ty 16), 8x8 micro-
// tile per thread via packed f32x2 (rows ty*4+{0..3}, 64+ty*4+{0..3}; cols
// 4tx+{0..3}, 64+4tx+{0..3}). As/Bs d-major + XOR swizzle; B double-buffered.
// ---------------------------------------------------------------------------
__global__ __launch_bounds__(THREADS, 1)
void vq_kernel(const float* __restrict__ z, const float* __restrict__ cb,
               float* __restrict__ zq, float* __restrict__ idx_out,
               int K, int write_idx) {
    extern __shared__ float smem[];
    float* As  = smem;                   // [D_DIM][BM] swizzled  (128 KB)
    float* Bs0 = As + D_DIM * BM;        // [BK][BN]  swizzled
    float* Bs1 = Bs0 + BK * BN;          // [BK][BN]
    float* redD = As;                    // aliases As (dead after main loop)
    int*   redI = (int*)(As + BM * 16);
    __shared__ int rowIdx[BM];

    const int tid = threadIdx.x;
    const int tx  = tid & 15;
    const int ty  = tid >> 4;
    const long m0 = (long)blockIdx.x * BM;

    const int NCHUNK = (K / BN) * (D_DIM / BK);   // 32 for K=1024

    // ---- stage z tile transposed: As[d][m] = z[m0+m][d] ----
    const float4* zsrc = (const float4*)(z + m0 * D_DIM);
    #pragma unroll 4
    for (int f = tid; f < BM * (D_DIM / 4); f += THREADS) {
        int m = f >> 6, d0 = (f & 63) * 4;
        float4 v = zsrc[f];
        As[(d0 + 0) * BM + swz(m, d0 + 0)] = v.x;
        As[(d0 + 1) * BM + swz(m, d0 + 1)] = v.y;
        As[(d0 + 2) * BM + swz(m, d0 + 2)] = v.z;
        As[(d0 + 3) * BM + swz(m, d0 + 3)] = v.w;
    }

    // ---- prefetch + stage B chunk 0 (codes 0..127, d 0..63) ----
    float4 pf[8];
    #pragma unroll
    for (int t = 0; t < 8; t++) {
        int f = tid + t * THREADS;            // r = f>>4 (code), c4 = f&15
        pf[t] = __ldg((const float4*)(cb + (size_t)(f >> 4) * D_DIM + (f & 15) * 4));
    }
    #pragma unroll
    for (int t = 0; t < 8; t++) {
        int f = tid + t * THREADS;
        int r = f >> 4, d0 = (f & 15) * 4;
        Bs0[(d0 + 0) * BN + swz(r, d0 + 0)] = pf[t].x;
        Bs0[(d0 + 1) * BN + swz(r, d0 + 1)] = pf[t].y;
        Bs0[(d0 + 2) * BN + swz(r, d0 + 2)] = pf[t].z;
        Bs0[(d0 + 3) * BN + swz(r, d0 + 3)] = pf[t].w;
    }
    __syncthreads();

    float bestD[8];
    int   bestI[8];
    #pragma unroll
    for (int i = 0; i < 8; i++) { bestD[i] = 3.4e38f; bestI[i] = 0; }

    // acc2[i][p]: row i (8), col-pair p (4): packed (col 2p, col 2p+1)
    unsigned long long acc2[8][4];

    for (int ck = 0; ck < NCHUNK; ++ck) {
        if ((ck & 3) == 0) {
            #pragma unroll
            for (int i = 0; i < 8; i++)
                #pragma unroll
                for (int p = 0; p < 4; p++) acc2[i][p] = 0ull;
        }

        // issue LDG prefetch of next chunk (overlaps compute)
        if (ck + 1 < NCHUNK) {
            int nck = ck + 1;
            const float* src = cb + (size_t)((nck >> 2) * BN) * D_DIM + (nck & 3) * BK;
            #pragma unroll
            for (int t = 0; t < 8; t++) {
                int f = tid + t * THREADS;
                pf[t] = __ldg((const float4*)(src + (size_t)(f >> 4) * D_DIM + (f & 15) * 4));
            }
        }

        const float* Bsc = (ck & 1) ? Bs1 : Bs0;
        const float* Asc = As + ((ck & 3) * BK) * BM;

        #pragma unroll 16
        for (int d = 0; d < BK; ++d) {
            const float* AsD = Asc + d * BM;
            const float* BsD = Bsc + d * BN;
            int s = d & 31;
            float4 a0 = *(const float4*)(AsD + (((ty      ) ^ s) << 2));
            float4 a1 = *(const float4*)(AsD + (((ty + 16) ^ s) << 2));
            // B float4 (x,y)/(z,w) pairs ARE the packed operands
            ulonglong2 b0 = *(const ulonglong2*)(BsD + (((tx      ) ^ s) << 2));
            ulonglong2 b1 = *(const ulonglong2*)(BsD + (((tx + 16) ^ s) << 2));
            unsigned long long aa[8];
            aa[0] = pack2(a0.x, a0.x); aa[1] = pack2(a0.y, a0.y);
            aa[2] = pack2(a0.z, a0.z); aa[3] = pack2(a0.w, a0.w);
            aa[4] = pack2(a1.x, a1.x); aa[5] = pack2(a1.y, a1.y);
            aa[6] = pack2(a1.z, a1.z); aa[7] = pack2(a1.w, a1.w);
            #pragma unroll
            for (int i = 0; i < 8; i++) {
                fma2(acc2[i][0], aa[i], b0.x);
                fma2(acc2[i][1], aa[i], b0.y);
                fma2(acc2[i][2], aa[i], b1.x);
                fma2(acc2[i][3], aa[i], b1.y);
            }
        }

        // stage prefetched chunk into alternate buffer; one sync per chunk
        if (ck + 1 < NCHUNK) {
            float* Bsn = (ck & 1) ? Bs0 : Bs1;
            #pragma unroll
            for (int t = 0; t < 8; t++) {
                int f = tid + t * THREADS;
                int r = f >> 4, d0 = (f & 15) * 4;
                Bsn[(d0 + 0) * BN + swz(r, d0 + 0)] = pf[t].x;
                Bsn[(d0 + 1) * BN + swz(r, d0 + 1)] = pf[t].y;
                Bsn[(d0 + 2) * BN + swz(r, d0 + 2)] = pf[t].z;
                Bsn[(d0 + 3) * BN + swz(r, d0 + 3)] = pf[t].w;
            }
            __syncthreads();
        }

        // argmin at code-tile boundary: dist = ||c||^2 - 2 z.c
        if ((ck & 3) == 3) {
            int n0 = (ck >> 2) * BN;
            #pragma unroll
            for (int p = 0; p < 4; p++) {
                int col0 = n0 + ((p < 2) ? (tx * 4 + 2 * p)
                                         : (64 + tx * 4 + 2 * (p - 2)));
                float cs0 = g_csq[col0];
                float cs1 = g_csq[col0 + 1];
                #pragma unroll
                for (int i = 0; i < 8; i++) {
                    float clo, chi;
                    unpack2(acc2[i][p], clo, chi);
                    float d0v = fmaf(-2.f, clo, cs0);
                    float d1v = fmaf(-2.f, chi, cs1);
                    if (d0v < bestD[i]) { bestD[i] = d0v; bestI[i] = col0; }
                    if (d1v < bestD[i]) { bestD[i] = d1v; bestI[i] = col0 + 1; }
                }
            }
        }
    }

    __syncthreads();   // main-loop reads of As done; safe to alias redD/redI

    // ---- cross-thread argmin per row (16 tx threads share each row) ----
    #pragma unroll
    for (int i = 0; i < 8; i++) {
        int row = (i < 4) ? (ty * 4 + i) : (64 + ty * 4 + i - 4);
        redD[row * 16 + tx] = bestD[i];
        redI[row * 16 + tx] = bestI[i];
    }
    __syncthreads();
    if (tid < BM) {
        float bd = redD[tid * 16];
        int   bi = redI[tid * 16];
        #pragma unroll
        for (int t = 1; t < 16; t++) {
            float d = redD[tid * 16 + t];
            int  ii = redI[tid * 16 + t];
            if (d < bd || (d == bd && ii < bi)) { bd = d; bi = ii; }
        }
        rowIdx[tid] = bi;
        if (write_idx) idx_out[m0 + tid] = (float)bi;
    }
    __syncthreads();

    // ---- gather z_q = codebook[idx] (coalesced float4) ----
    float4* zqdst = (float4*)(zq + m0 * D_DIM);
    #pragma unroll 4
    for (int f = tid; f < BM * (D_DIM / 4); f += THREADS) {
        float4 v = __ldg((const float4*)(cb + (size_t)rowIdx[f >> 6] * D_DIM + (f & 63) * 4));
        zqdst[f] = v;
    }
}

// ---------------------------------------------------------------------------
extern "C" void kernel_launch(void* const* d_in, const int* in_sizes, int n_in,
                              void* d_out, int out_size) {
    const float* z  = (const float*)d_in[0];
    const float* cb = (const float*)d_in[1];
    const int zElems  = in_sizes[0];
    const int cbElems = in_sizes[1];
    const int ntok = zElems / D_DIM;
    const int K    = cbElems / D_DIM;

    float* out     = (float*)d_out;
    float* idx_out = out + (size_t)zElems;
    const int write_idx = (out_size >= zElems + ntok) ? 1 : 0;

    csq_kernel<<<(K + 7) / 8, 256>>>(cb, K);

    const int smemBytes = (D_DIM * BM + 2 * BK * BN) * (int)sizeof(float);
    cudaFuncSetAttribute(vq_kernel,
                         cudaFuncAttributeMaxDynamicSharedMemorySize, smemBytes);
    vq_kernel<<<ntok / BM, THREADS, smemBytes>>>(z, cb, out, idx_out, K, write_idx);
}

// round 9
// speedup vs baseline: 2.2081x; 1.0303x over previous
#include <cuda_runtime.h>

#define THREADS 512
#define BM 128          // tokens per block
#define BN 128          // codes per tile
#define BK 64           // d-chunk
#define D_DIM 256
#define ASTR 260        // floats per As row (256+4): float4-aligned, bank-spread
#define BSTR 68         // floats per Bs row (64+4):  17*k mod 32 distinct

__device__ float g_csq[4096];   // ||c_k||^2, K <= 4096

// ---- packed f32x2: one issue slot, two fp32 FMA lanes, zero pack MOVs ----
__device__ __forceinline__ void fma2(unsigned long long& d,
                                     unsigned long long a, unsigned long long b) {
    asm("fma.rn.f32x2 %0, %1, %2, %0;" : "+l"(d) : "l"(a), "l"(b));
}
__device__ __forceinline__ void unpack2(unsigned long long v, float& lo, float& hi) {
    asm("mov.b64 {%0, %1}, %2;" : "=f"(lo), "=f"(hi) : "l"(v));
}

// ---------------------------------------------------------------------------
__global__ void csq_kernel(const float* __restrict__ cb, int K) {
    int k = blockIdx.x * (blockDim.x / 32) + (threadIdx.x >> 5);
    int lane = threadIdx.x & 31;
    if (k >= K) return;
    const float* row = cb + (size_t)k * D_DIM;
    float s = 0.f;
    #pragma unroll
    for (int d = lane; d < D_DIM; d += 32) {
        float v = row[d];
        s = fmaf(v, v, s);
    }
    #pragma unroll
    for (int o = 16; o; o >>= 1) s += __shfl_xor_sync(0xffffffffu, s, o);
    if (lane == 0) g_csq[k] = s;
}

// ---------------------------------------------------------------------------
// Fused GEMM + argmin + gather, K-dim f32x2 packing.
// 512 threads = (tx=tid&31) x (ty=tid>>5).
// Rows: 4ty+i (i<4) and 64+4ty+i  -> warp broadcast on A.
// Cols: tx+32j (j<4)              -> 17*(tx+32j) mod 32 all-distinct on B.
// acc2[i][j] holds packed (even-d, odd-d) partial dot products.
// ---------------------------------------------------------------------------
__global__ __launch_bounds__(THREADS, 1)
void vq_kernel(const float* __restrict__ z, const float* __restrict__ cb,
               float* __restrict__ zq, float* __restrict__ idx_out,
               int K, int write_idx) {
    extern __shared__ float smem[];
    float* As  = smem;                   // [BM][ASTR]  row-major, 133 KB
    float* Bs0 = As + BM * ASTR;         // [BN][BSTR]  34.8 KB
    float* Bs1 = Bs0 + BN * BSTR;
    float* redD = As;                    // aliases As (dead after main loop)
    int*   redI = (int*)(As + BM * 32);
    __shared__ int rowIdx[BM];

    const int tid = threadIdx.x;
    const int tx  = tid & 31;
    const int ty  = tid >> 5;
    const long m0 = (long)blockIdx.x * BM;

    const int NCHUNK = (K / BN) * (D_DIM / BK);   // 32 for K=1024

    // ---- stage z tile row-major: As[m][d] ----
    const float4* zsrc = (const float4*)(z + m0 * D_DIM);
    #pragma unroll 4
    for (int f = tid; f < BM * (D_DIM / 4); f += THREADS) {
        int m = f >> 6, c4 = f & 63;
        *(float4*)&As[m * ASTR + c4 * 4] = zsrc[f];
    }

    // ---- prefetch + stage B chunk 0 (codes 0..127, d 0..63) ----
    float4 pf[4];
    #pragma unroll
    for (int t = 0; t < 4; t++) {
        int f = tid + t * THREADS;            // r = f>>4 (code), c4 = f&15
        pf[t] = __ldg((const float4*)(cb + (size_t)(f >> 4) * D_DIM + (f & 15) * 4));
    }
    #pragma unroll
    for (int t = 0; t < 4; t++) {
        int f = tid + t * THREADS;
        *(float4*)&Bs0[(f >> 4) * BSTR + (f & 15) * 4] = pf[t];
    }
    __syncthreads();

    float bestD[8];
    int   bestI[8];
    #pragma unroll
    for (int i = 0; i < 8; i++) { bestD[i] = 3.4e38f; bestI[i] = 0; }

    unsigned long long acc2[8][4];   // 8 rows x 4 cols, packed over d-pairs

    for (int ck = 0; ck < NCHUNK; ++ck) {
        if ((ck & 3) == 0) {
            #pragma unroll
            for (int i = 0; i < 8; i++)
                #pragma unroll
                for (int j = 0; j < 4; j++) acc2[i][j] = 0ull;
        }

        // LDG prefetch of next chunk (overlaps compute)
        if (ck + 1 < NCHUNK) {
            int nck = ck + 1;
            const float* src = cb + (size_t)((nck >> 2) * BN) * D_DIM + (nck & 3) * BK;
            #pragma unroll
            for (int t = 0; t < 4; t++) {
                int f = tid + t * THREADS;
                pf[t] = __ldg((const float4*)(src + (size_t)(f >> 4) * D_DIM + (f & 15) * 4));
            }
        }

        const float* Bsc = (ck & 1) ? Bs1 : Bs0;
        const int dbase = (ck & 3) * BK;
        const float* Ap0 = As + (4 * ty) * ASTR + dbase;          // rows 4ty+i
        const float* Ap1 = Ap0 + 64 * ASTR;                       // rows 64+4ty+i
        const float* Bp  = Bsc + tx * BSTR;                       // col tx+32j

        #pragma unroll
        for (int dq = 0; dq < BK / 4; ++dq) {
            const int doff = dq * 4;
            ulonglong2 b[4];
            #pragma unroll
            for (int j = 0; j < 4; j++)
                b[j] = *(const ulonglong2*)(Bp + (32 * j) * BSTR + doff);
            ulonglong2 a[8];
            #pragma unroll
            for (int i = 0; i < 4; i++) {
                a[i]     = *(const ulonglong2*)(Ap0 + i * ASTR + doff);
                a[i + 4] = *(const ulonglong2*)(Ap1 + i * ASTR + doff);
            }
            #pragma unroll
            for (int i = 0; i < 8; i++)
                #pragma unroll
                for (int j = 0; j < 4; j++) {
                    fma2(acc2[i][j], a[i].x, b[j].x);
                    fma2(acc2[i][j], a[i].y, b[j].y);
                }
        }

        // stage prefetched chunk; one sync per chunk
        if (ck + 1 < NCHUNK) {
            float* Bsn = (ck & 1) ? Bs0 : Bs1;
            #pragma unroll
            for (int t = 0; t < 4; t++) {
                int f = tid + t * THREADS;
                *(float4*)&Bsn[(f >> 4) * BSTR + (f & 15) * 4] = pf[t];
            }
            __syncthreads();
        }

        // argmin at code-tile boundary: dist = ||c||^2 - 2 z.c
        if ((ck & 3) == 3) {
            int n0 = (ck >> 2) * BN;
            #pragma unroll
            for (int j = 0; j < 4; j++) {
                int col = n0 + tx + 32 * j;
                float cs = g_csq[col];
                #pragma unroll
                for (int i = 0; i < 8; i++) {
                    float lo, hi;
                    unpack2(acc2[i][j], lo, hi);
                    float dist = fmaf(-2.f, lo + hi, cs);
                    if (dist < bestD[i]) { bestD[i] = dist; bestI[i] = col; }
                }
            }
        }
    }

    __syncthreads();   // main-loop reads of As done; safe to alias redD/redI

    // ---- cross-thread argmin per row (32 tx threads share each row) ----
    #pragma unroll
    for (int i = 0; i < 8; i++) {
        int row = (i < 4) ? (4 * ty + i) : (64 + 4 * ty + i - 4);
        redD[row * 32 + tx] = bestD[i];
        redI[row * 32 + tx] = bestI[i];
    }
    __syncthreads();
    if (tid < BM) {
        float bd = redD[tid * 32];
        int   bi = redI[tid * 32];
        #pragma unroll
        for (int t = 1; t < 32; t++) {
            float d = redD[tid * 32 + t];
            int  ii = redI[tid * 32 + t];
            if (d < bd || (d == bd && ii < bi)) { bd = d; bi = ii; }
        }
        rowIdx[tid] = bi;
        if (write_idx) idx_out[m0 + tid] = (float)bi;
    }
    __syncthreads();

    // ---- gather z_q = codebook[idx] (coalesced float4) ----
    float4* zqdst = (float4*)(zq + m0 * D_DIM);
    #pragma unroll 2
    for (int f = tid; f < BM * (D_DIM / 4); f += THREADS) {
        float4 v = __ldg((const float4*)(cb + (size_t)rowIdx[f >> 6] * D_DIM + (f & 63) * 4));
        zqdst[f] = v;
    }
}

// ---------------------------------------------------------------------------
extern "C" void kernel_launch(void* const* d_in, const int* in_sizes, int n_in,
                              void* d_out, int out_size) {
    const float* z  = (const float*)d_in[0];
    const float* cb = (const float*)d_in[1];
    const int zElems  = in_sizes[0];
    const int cbElems = in_sizes[1];
    const int ntok = zElems / D_DIM;
    const int K    = cbElems / D_DIM;

    float* out     = (float*)d_out;
    float* idx_out = out + (size_t)zElems;
    const int write_idx = (out_size >= zElems + ntok) ? 1 : 0;

    csq_kernel<<<(K + 7) / 8, 256>>>(cb, K);

    const int smemBytes = (BM * ASTR + 2 * BN * BSTR) * (int)sizeof(float);
    cudaFuncSetAttribute(vq_kernel,
                         cudaFuncAttributeMaxDynamicSharedMemorySize, smemBytes);
    vq_kernel<<<ntok / BM, THREADS, smemBytes>>>(z, cb, out, idx_out, K, write_idx);
}

// round 11
// speedup vs baseline: 2.5084x; 1.1360x over previous
#include <cuda_runtime.h>
#include <cuda_bf16.h>
#include <cstdint>

#define D_DIM   256
#define BM      64            // tokens per CTA
#define BN      32            // codes per iteration
#define THREADS 256

#define ZROWB   528           // 264 bf16 row stride: 16B-groups stride 33 (odd) -> ldmatrix conflict-free
#define ZSPLIT  (64 * ZROWB)  // 33792 B per z split
#define BSPLIT  (32 * ZROWB)  // 16896 B per B split
#define BBUF    (3 * BSPLIT)  // 50688 B per B buffer
#define OFF_B   (3 * ZSPLIT)  // 101376
#define SMEM_SZ (OFF_B + 2 * BBUF)   // 202752 B

__device__ float         g_csq[4096];
__device__ __nv_bfloat16 g_cbH[4096 * 256];
__device__ __nv_bfloat16 g_cbM[4096 * 256];
__device__ __nv_bfloat16 g_cbL[4096 * 256];

// ---------------- helpers -------------------------------------------------
__device__ __forceinline__ uint32_t smem_u32(const void* p) {
    uint32_t a;
    asm("{ .reg .u64 t; cvta.to.shared.u64 t, %1; cvt.u32.u64 %0, t; }"
        : "=r"(a) : "l"(p));
    return a;
}
__device__ __forceinline__ void split3(float v, __nv_bfloat16& h,
                                       __nv_bfloat16& m, __nv_bfloat16& l) {
    h = __float2bfloat16_rn(v);
    float r1 = v - __bfloat162float(h);
    m = __float2bfloat16_rn(r1);
    float r2 = r1 - __bfloat162float(m);
    l = __float2bfloat16_rn(r2);
}
__device__ __forceinline__ uint32_t packb(__nv_bfloat16 lo, __nv_bfloat16 hi) {
    return ((uint32_t)__bfloat16_as_ushort(hi) << 16) | __bfloat16_as_ushort(lo);
}
__device__ __forceinline__ void split2pack(float a, float b, uint32_t& H,
                                           uint32_t& M, uint32_t& L) {
    __nv_bfloat16 h0, m0, l0, h1, m1, l1;
    split3(a, h0, m0, l0);
    split3(b, h1, m1, l1);
    H = packb(h0, h1); M = packb(m0, m1); L = packb(l0, l1);
}
__device__ __forceinline__ void ldsm4(uint32_t* r, uint32_t a) {
    asm volatile("ldmatrix.sync.aligned.m8n8.x4.shared.b16 {%0,%1,%2,%3}, [%4];"
                 : "=r"(r[0]), "=r"(r[1]), "=r"(r[2]), "=r"(r[3]) : "r"(a));
}
__device__ __forceinline__ void mma16816(float* c, const uint32_t* a,
                                         uint32_t b0, uint32_t b1) {
    asm volatile(
        "mma.sync.aligned.m16n8k16.row.col.f32.bf16.bf16.f32 "
        "{%0,%1,%2,%3}, {%4,%5,%6,%7}, {%8,%9}, {%0,%1,%2,%3};"
        : "+f"(c[0]), "+f"(c[1]), "+f"(c[2]), "+f"(c[3])
        : "r"(a[0]), "r"(a[1]), "r"(a[2]), "r"(a[3]), "r"(b0), "r"(b1));
}
__device__ __forceinline__ void cp16(uint32_t dst, const void* src) {
    asm volatile("cp.async.cg.shared.global [%0], [%1], 16;"
                 :: "r"(dst), "l"(src) : "memory");
}
#define CP_COMMIT() asm volatile("cp.async.commit_group;" ::: "memory")
#define CP_WAIT0()  asm volatile("cp.async.wait_group 0;" ::: "memory")

// ---------------- prologue kernels ----------------------------------------
__global__ void prep_cb_kernel(const float* __restrict__ cb, int n) {
    int i = blockIdx.x * blockDim.x + threadIdx.x;
    if (i >= n) return;
    __nv_bfloat16 h, m, l;
    split3(cb[i], h, m, l);
    g_cbH[i] = h; g_cbM[i] = m; g_cbL[i] = l;
}
__global__ void csq_kernel(const float* __restrict__ cb, int K) {
    int k = blockIdx.x * (blockDim.x / 32) + (threadIdx.x >> 5);
    int lane = threadIdx.x & 31;
    if (k >= K) return;
    const float* row = cb + (size_t)k * D_DIM;
    float s = 0.f;
    #pragma unroll
    for (int d = lane; d < D_DIM; d += 32) {
        float v = row[d];
        s = fmaf(v, v, s);
    }
    #pragma unroll
    for (int o = 16; o; o >>= 1) s += __shfl_xor_sync(0xffffffffu, s, o);
    if (lane == 0) g_csq[k] = s;
}

// ---------------- main kernel ---------------------------------------------
// 8 warps: wm = wid>>1 (token rows 16*wm..), wn = wid&1 (codes 16*wn..).
// 3-split bf16, 6 products per accumulator group -> fp32-grade distances.
__global__ __launch_bounds__(THREADS, 1)
void vq_kernel(const float* __restrict__ z, const float* __restrict__ cb,
               float* __restrict__ zq, float* __restrict__ idx_out,
               int K, int write_idx) {
    extern __shared__ char smem[];
    const uint32_t sbase = smem_u32(smem);

    const int tid  = threadIdx.x;
    const int lane = tid & 31;
    const int wid  = tid >> 5;
    const int wm   = wid >> 1;
    const int wn   = wid & 1;
    const long m0  = (long)blockIdx.x * BM;
    const int NT   = K / BN;

    // ---- issue cp.async for B tile 0 (3 splits, 32 codes x 256 d bf16) ----
    {
        const uint32_t dstb = sbase + OFF_B;
        #pragma unroll
        for (int q = 0; q < 4; q++) {
            int f = tid + q * THREADS;        // uint4 index: 1024 per split
            int r = f >> 5, c16 = f & 31;     // 32x 16B per 512B row
            size_t gb = (size_t)r * 512 + (size_t)c16 * 16;  // bytes into split
            uint32_t db = (uint32_t)(r * ZROWB + c16 * 16);
            cp16(dstb + 0 * BSPLIT + db, (const char*)g_cbH + gb);
            cp16(dstb + 1 * BSPLIT + db, (const char*)g_cbM + gb);
            cp16(dstb + 2 * BSPLIT + db, (const char*)g_cbL + gb);
        }
        CP_COMMIT();
    }

    // ---- stage z splits into smem (row = tid>>2, 64 dims per thread) ----
    {
        int row = tid >> 2, seg = tid & 3;
        const float4* zr = (const float4*)(z + (m0 + row) * D_DIM) + seg * 16;
        char* zb = smem + row * ZROWB + seg * 128;
        #pragma unroll
        for (int q = 0; q < 16; q++) {
            float4 f = __ldg(zr + q);
            uint32_t H0, M0, L0, H1, M1, L1;
            split2pack(f.x, f.y, H0, M0, L0);
            split2pack(f.z, f.w, H1, M1, L1);
            *(uint32_t*)(zb + 0 * ZSPLIT + q * 8)     = H0;
            *(uint32_t*)(zb + 0 * ZSPLIT + q * 8 + 4) = H1;
            *(uint32_t*)(zb + 1 * ZSPLIT + q * 8)     = M0;
            *(uint32_t*)(zb + 1 * ZSPLIT + q * 8 + 4) = M1;
            *(uint32_t*)(zb + 2 * ZSPLIT + q * 8)     = L0;
            *(uint32_t*)(zb + 2 * ZSPLIT + q * 8 + 4) = L1;
        }
    }
    CP_WAIT0();
    __syncthreads();

    // ldmatrix base addresses (thread t: row = t&15, k-half = t>>4)
    const int lr = lane & 15, lh = lane >> 4;
    const uint32_t aAddr = sbase + (uint32_t)(wm * 16 + lr) * ZROWB + lh * 16;
    const uint32_t bAddr0 = sbase + OFF_B + (uint32_t)(wn * 16 + lr) * ZROWB + lh * 16;

    // product list (z-split, c-split): hh, hm, mh, mm, hl, lh
    float b0D = 3.4e38f, b1D = 3.4e38f;
    int   b0I = 0, b1I = 0;

    for (int t = 0; t < NT; ++t) {
        // prefetch next B tile into alternate buffer
        if (t + 1 < NT) {
            const uint32_t dstb = sbase + OFF_B + (uint32_t)((t + 1) & 1) * BBUF;
            size_t nbase = (size_t)(t + 1) * BN * 512;    // bytes into split arrays
            #pragma unroll
            for (int q = 0; q < 4; q++) {
                int f = tid + q * THREADS;
                int r = f >> 5, c16 = f & 31;
                size_t gb = nbase + (size_t)r * 512 + (size_t)c16 * 16;
                uint32_t db = (uint32_t)(r * ZROWB + c16 * 16);
                cp16(dstb + 0 * BSPLIT + db, (const char*)g_cbH + gb);
                cp16(dstb + 1 * BSPLIT + db, (const char*)g_cbM + gb);
                cp16(dstb + 2 * BSPLIT + db, (const char*)g_cbL + gb);
            }
            CP_COMMIT();
        }

        const uint32_t bAddr = bAddr0 + (uint32_t)(t & 1) * BBUF;

        float acc[2][6][4];
        #pragma unroll
        for (int tl = 0; tl < 2; tl++)
            #pragma unroll
            for (int p = 0; p < 6; p++)
                #pragma unroll
                for (int r = 0; r < 4; r++) acc[tl][p][r] = 0.f;

        #pragma unroll
        for (int kk = 0; kk < 16; ++kk) {
            uint32_t aF[3][4], bF[3][4];
            #pragma unroll
            for (int s = 0; s < 3; s++)
                ldsm4(aF[s], aAddr + s * ZSPLIT + kk * 32);
            #pragma unroll
            for (int s = 0; s < 3; s++)
                ldsm4(bF[s], bAddr + s * BSPLIT + kk * 32);
            // products: (0,0) (0,1) (1,0) (1,1) (0,2) (2,0)
            #pragma unroll
            for (int p = 0; p < 6; p++) {
                const int sa = (p == 2 || p == 3) ? 1 : (p == 5 ? 2 : 0);
                const int sb = (p == 1 || p == 3) ? 1 : (p == 4 ? 2 : 0);
                mma16816(acc[0][p], aF[sa], bF[sb][0], bF[sb][2]);
                mma16816(acc[1][p], aF[sa], bF[sb][1], bF[sb][3]);
            }
        }

        // per-tile argmin: dist = ||c||^2 - 2 z.c  (||z||^2 row-constant)
        const int n0 = t * BN;
        #pragma unroll
        for (int tl = 0; tl < 2; tl++) {
            float c0 = 0.f, c1 = 0.f, c2 = 0.f, c3 = 0.f;
            #pragma unroll
            for (int p = 0; p < 6; p++) {
                c0 += acc[tl][p][0]; c1 += acc[tl][p][1];
                c2 += acc[tl][p][2]; c3 += acc[tl][p][3];
            }
            int colb = n0 + wn * 16 + tl * 8 + 2 * (lane & 3);
            float q0 = g_csq[colb], q1 = g_csq[colb + 1];
            float d0 = fmaf(-2.f, c0, q0);
            float d1 = fmaf(-2.f, c1, q1);
            float d2 = fmaf(-2.f, c2, q0);
            float d3 = fmaf(-2.f, c3, q1);
            if (d0 < b0D) { b0D = d0; b0I = colb; }
            if (d1 < b0D) { b0D = d1; b0I = colb + 1; }
            if (d2 < b1D) { b1D = d2; b1I = colb; }
            if (d3 < b1D) { b1D = d3; b1I = colb + 1; }
        }

        if (t + 1 < NT) CP_WAIT0();
        __syncthreads();
    }

    // ---- cross-thread argmin (8 slots per token row), aliasing z smem ----
    float* redD   = (float*)smem;            // [64][8]
    int*   redI   = (int*)(smem + 2048);     // [64][8]
    int*   rowIdx = (int*)(smem + 4096);     // [64]
    {
        int g = lane >> 2;
        int slot = wn * 4 + (lane & 3);
        int r0 = wm * 16 + g;
        redD[r0 * 8 + slot] = b0D;  redI[r0 * 8 + slot] = b0I;
        redD[(r0 + 8) * 8 + slot] = b1D;  redI[(r0 + 8) * 8 + slot] = b1I;
    }
    __syncthreads();
    if (tid < BM) {
        float bd = redD[tid * 8];
        int   bi = redI[tid * 8];
        #pragma unroll
        for (int s = 1; s < 8; s++) {
            float d = redD[tid * 8 + s];
            int  ii = redI[tid * 8 + s];
            if (d < bd || (d == bd && ii < bi)) { bd = d; bi = ii; }
        }
        rowIdx[tid] = bi;
        if (write_idx) idx_out[m0 + tid] = (float)bi;
    }
    __syncthreads();

    // ---- gather z_q = codebook[idx] from exact fp32 codebook ----
    float4* zqdst = (float4*)(zq + m0 * D_DIM);
    #pragma unroll 4
    for (int f = tid; f < BM * (D_DIM / 4); f += THREADS) {
        float4 v = __ldg((const float4*)(cb + (size_t)rowIdx[f >> 6] * D_DIM + (f & 63) * 4));
        zqdst[f] = v;
    }
}

// ---------------------------------------------------------------------------
extern "C" void kernel_launch(void* const* d_in, const int* in_sizes, int n_in,
                              void* d_out, int out_size) {
    const float* z  = (const float*)d_in[0];
    const float* cb = (const float*)d_in[1];
    const int zElems  = in_sizes[0];
    const int cbElems = in_sizes[1];
    const int ntok = zElems / D_DIM;
    const int K    = cbElems / D_DIM;

    float* out     = (float*)d_out;
    float* idx_out = out + (size_t)zElems;
    const int write_idx = (out_size >= zElems + ntok) ? 1 : 0;

    csq_kernel<<<(K + 7) / 8, 256>>>(cb, K);
    prep_cb_kernel<<<(cbElems + 255) / 256, 256>>>(cb, cbElems);

    cudaFuncSetAttribute(vq_kernel,
                         cudaFuncAttributeMaxDynamicSharedMemorySize, SMEM_SZ);
    vq_kernel<<<ntok / BM, THREADS, SMEM_SZ>>>(z, cb, out, idx_out, K, write_idx);
}

// round 13
// speedup vs baseline: 4.4431x; 1.7713x over previous
#include <cuda_runtime.h>
#include <cuda_fp16.h>
#include <cstdint>

#define D_DIM   256
#define BM      64            // tokens per CTA
#define BN      64            // codes per iteration (2 warps x n32)
#define THREADS 256

#define ZROWB   528           // 256 fp16 = 512B + 16B pad: odd 16B stride -> ldsm conflict-free
#define ZSPLIT  (64 * ZROWB)  // 33792 B per z split (h, l)
#define BSPLIT  (64 * ZROWB)  // 33792 B per B split per buffer
#define BBUF    (2 * BSPLIT)  // 67584 B per B buffer (h + l)
#define OFF_B   (2 * ZSPLIT)  // 67584
#define SMEM_SZ (OFF_B + 2 * BBUF)   // 202752 B

__device__ float  g_csq[4096];
__device__ __half g_cbH[4096 * 256];
__device__ __half g_cbL[4096 * 256];

// ---------------- helpers -------------------------------------------------
__device__ __forceinline__ uint32_t smem_u32(const void* p) {
    uint32_t a;
    asm("{ .reg .u64 t; cvta.to.shared.u64 t, %1; cvt.u32.u64 %0, t; }"
        : "=r"(a) : "l"(p));
    return a;
}
__device__ __forceinline__ void split2(float v, __half& h, __half& l) {
    h = __float2half_rn(v);
    l = __float2half_rn(v - __half2float(h));   // v-h exact in fp32
}
__device__ __forceinline__ uint32_t packh(__half lo, __half hi) {
    return ((uint32_t)__half_as_ushort(hi) << 16) | __half_as_ushort(lo);
}
__device__ __forceinline__ void ldsm4(uint32_t* r, uint32_t a) {
    asm volatile("ldmatrix.sync.aligned.m8n8.x4.shared.b16 {%0,%1,%2,%3}, [%4];"
                 : "=r"(r[0]), "=r"(r[1]), "=r"(r[2]), "=r"(r[3]) : "r"(a));
}
__device__ __forceinline__ void mma16816(float* c, const uint32_t* a,
                                         uint32_t b0, uint32_t b1) {
    asm volatile(
        "mma.sync.aligned.m16n8k16.row.col.f32.f16.f16.f32 "
        "{%0,%1,%2,%3}, {%4,%5,%6,%7}, {%8,%9}, {%0,%1,%2,%3};"
        : "+f"(c[0]), "+f"(c[1]), "+f"(c[2]), "+f"(c[3])
        : "r"(a[0]), "r"(a[1]), "r"(a[2]), "r"(a[3]), "r"(b0), "r"(b1));
}
__device__ __forceinline__ void cp16(uint32_t dst, const void* src) {
    asm volatile("cp.async.cg.shared.global [%0], [%1], 16;"
                 :: "r"(dst), "l"(src) : "memory");
}
#define CP_COMMIT() asm volatile("cp.async.commit_group;" ::: "memory")
#define CP_WAIT0()  asm volatile("cp.async.wait_group 0;" ::: "memory")

// ---------------- prologue kernels ----------------------------------------
__global__ void prep_cb_kernel(const float* __restrict__ cb, int n) {
    int i = blockIdx.x * blockDim.x + threadIdx.x;
    if (i >= n) return;
    __half h, l;
    split2(cb[i], h, l);
    g_cbH[i] = h; g_cbL[i] = l;
}
__global__ void csq_kernel(const float* __restrict__ cb, int K) {
    int k = blockIdx.x * (blockDim.x / 32) + (threadIdx.x >> 5);
    int lane = threadIdx.x & 31;
    if (k >= K) return;
    const float* row = cb + (size_t)k * D_DIM;
    float s = 0.f;
    #pragma unroll
    for (int d = lane; d < D_DIM; d += 32) {
        float v = row[d];
        s = fmaf(v, v, s);
    }
    #pragma unroll
    for (int o = 16; o; o >>= 1) s += __shfl_xor_sync(0xffffffffu, s, o);
    if (lane == 0) g_csq[k] = s;
}

// ---------------- main kernel ---------------------------------------------
// 8 warps: wm = wid>>1 (token rows 16*wm..), wn = wid&1 (codes 32*wn..).
// fp16 2-split, 3 products (hh, hl, lh) chained into one fp32 accumulator
// per n8 group -> fp32-grade distances at half the MMA count of bf16x6.
__global__ __launch_bounds__(THREADS, 1)
void vq_kernel(const float* __restrict__ z, const float* __restrict__ cb,
               float* __restrict__ zq, float* __restrict__ idx_out,
               int K, int write_idx) {
    extern __shared__ char smem[];
    const uint32_t sbase = smem_u32(smem);

    const int tid  = threadIdx.x;
    const int lane = tid & 31;
    const int wid  = tid >> 5;
    const int wm   = wid >> 1;
    const int wn   = wid & 1;
    const long m0  = (long)blockIdx.x * BM;
    const int NT   = K / BN;               // 16

    // ---- stage z splits into smem (row = tid>>2, 64 dims per thread) ----
    {
        int row = tid >> 2, seg = tid & 3;
        const float4* zr = (const float4*)(z + (m0 + row) * D_DIM) + seg * 16;
        char* zb = smem + row * ZROWB + seg * 128;
        float4 fv[16];
        #pragma unroll
        for (int q = 0; q < 16; q++) fv[q] = __ldg(zr + q);   // z LDGs first

        // ---- issue cp.async for B tile 0 while z converts ----
        {
            const uint32_t dstb = sbase + OFF_B;
            #pragma unroll
            for (int q = 0; q < 8; q++) {
                int f = tid + q * THREADS;        // [0, 2048)
                int r = f >> 5, c16 = f & 31;     // 64 rows x 32 16B-chunks
                size_t gb = (size_t)r * 512 + (size_t)c16 * 16;
                uint32_t db = (uint32_t)(r * ZROWB + c16 * 16);
                cp16(dstb + 0 * BSPLIT + db, (const char*)g_cbH + gb);
                cp16(dstb + 1 * BSPLIT + db, (const char*)g_cbL + gb);
            }
            CP_COMMIT();
        }

        #pragma unroll
        for (int q = 0; q < 16; q++) {
            float4 f = fv[q];
            __half h0, l0, h1, l1, h2, l2, h3, l3;
            split2(f.x, h0, l0); split2(f.y, h1, l1);
            split2(f.z, h2, l2); split2(f.w, h3, l3);
            *(uint32_t*)(zb + 0 * ZSPLIT + q * 8)     = packh(h0, h1);
            *(uint32_t*)(zb + 0 * ZSPLIT + q * 8 + 4) = packh(h2, h3);
            *(uint32_t*)(zb + 1 * ZSPLIT + q * 8)     = packh(l0, l1);
            *(uint32_t*)(zb + 1 * ZSPLIT + q * 8 + 4) = packh(l2, l3);
        }
    }
    CP_WAIT0();
    __syncthreads();

    // ldmatrix addresses (thread t: row = t&15, k-half = t>>4)
    const int lr = lane & 15, lh = lane >> 4;
    const uint32_t aAddr  = sbase + (uint32_t)(wm * 16 + lr) * ZROWB + lh * 16;
    const uint32_t bAddr0 = sbase + OFF_B
                          + (uint32_t)(wn * 32 + lr) * ZROWB + lh * 16;

    float bD[2] = {3.4e38f, 3.4e38f};     // row lane>>2, row lane>>2 + 8
    int   bI[2] = {0, 0};

    for (int t = 0; t < NT; ++t) {
        // prefetch next B tile into alternate buffer
        if (t + 1 < NT) {
            const uint32_t dstb = sbase + OFF_B + (uint32_t)((t + 1) & 1) * BBUF;
            size_t nbase = (size_t)(t + 1) * BN * 512;
            #pragma unroll
            for (int q = 0; q < 8; q++) {
                int f = tid + q * THREADS;
                int r = f >> 5, c16 = f & 31;
                size_t gb = nbase + (size_t)r * 512 + (size_t)c16 * 16;
                uint32_t db = (uint32_t)(r * ZROWB + c16 * 16);
                cp16(dstb + 0 * BSPLIT + db, (const char*)g_cbH + gb);
                cp16(dstb + 1 * BSPLIT + db, (const char*)g_cbL + gb);
            }
            CP_COMMIT();
        }

        const uint32_t bAddr = bAddr0 + (uint32_t)(t & 1) * BBUF;

        float acc[4][4];                  // 4 n8 groups (n32 per warp)
        #pragma unroll
        for (int g = 0; g < 4; g++)
            #pragma unroll
            for (int r = 0; r < 4; r++) acc[g][r] = 0.f;

        #pragma unroll
        for (int kk = 0; kk < 16; ++kk) {
            uint32_t aH[4], aL[4];
            ldsm4(aH, aAddr + 0 * ZSPLIT + kk * 32);
            ldsm4(aL, aAddr + 1 * ZSPLIT + kk * 32);
            #pragma unroll
            for (int h = 0; h < 2; h++) {          // 16-code halves of n32
                uint32_t bH[4], bL[4];
                uint32_t ba = bAddr + (uint32_t)(h * 16) * ZROWB + kk * 32;
                ldsm4(bH, ba + 0 * BSPLIT);
                ldsm4(bL, ba + 1 * BSPLIT);
                #pragma unroll
                for (int s = 0; s < 2; s++) {      // n8 within 16 codes
                    float* a = acc[h * 2 + s];
                    mma16816(a, aH, bH[s], bH[s + 2]);   // hh
                    mma16816(a, aH, bL[s], bL[s + 2]);   // hl
                    mma16816(a, aL, bH[s], bH[s + 2]);   // lh
                }
            }
        }

        // per-tile argmin: dist = ||c||^2 - 2 z.c  (||z||^2 row-constant)
        const int n0 = t * BN;
        #pragma unroll
        for (int g = 0; g < 4; g++) {
            int colb = n0 + wn * 32 + (g >> 1) * 16 + (g & 1) * 8 + 2 * (lane & 3);
            float q0 = g_csq[colb], q1 = g_csq[colb + 1];
            float d0 = fmaf(-2.f, acc[g][0], q0);
            float d1 = fmaf(-2.f, acc[g][1], q1);
            float d2 = fmaf(-2.f, acc[g][2], q0);
            float d3 = fmaf(-2.f, acc[g][3], q1);
            if (d0 < bD[0]) { bD[0] = d0; bI[0] = colb; }
            if (d1 < bD[0]) { bD[0] = d1; bI[0] = colb + 1; }
            if (d2 < bD[1]) { bD[1] = d2; bI[1] = colb; }
            if (d3 < bD[1]) { bD[1] = d3; bI[1] = colb + 1; }
        }

        if (t + 1 < NT) CP_WAIT0();
        __syncthreads();
    }

    // ---- cross-thread argmin (8 slots per token row), aliasing z smem ----
    float* redD   = (float*)smem;            // [64][8]
    int*   redI   = (int*)(smem + 2048);     // [64][8]
    int*   rowIdx = (int*)(smem + 4096);     // [64]
    {
        int g = lane >> 2;
        int slot = wn * 4 + (lane & 3);
        int r0 = wm * 16 + g;
        redD[r0 * 8 + slot] = bD[0];        redI[r0 * 8 + slot] = bI[0];
        redD[(r0 + 8) * 8 + slot] = bD[1];  redI[(r0 + 8) * 8 + slot] = bI[1];
    }
    __syncthreads();
    if (tid < BM) {
        float bd = redD[tid * 8];
        int   bi = redI[tid * 8];
        #pragma unroll
        for (int s = 1; s < 8; s++) {
            float d = redD[tid * 8 + s];
            int  ii = redI[tid * 8 + s];
            if (d < bd || (d == bd && ii < bi)) { bd = d; bi = ii; }
        }
        rowIdx[tid] = bi;
        if (write_idx) idx_out[m0 + tid] = (float)bi;
    }
    __syncthreads();

    // ---- gather z_q = codebook[idx] from exact fp32 codebook ----
    float4* zqdst = (float4*)(zq + m0 * D_DIM);
    #pragma unroll 4
    for (int f = tid; f < BM * (D_DIM / 4); f += THREADS) {
        float4 v = __ldg((const float4*)(cb + (size_t)rowIdx[f >> 6] * D_DIM + (f & 63) * 4));
        zqdst[f] = v;
    }
}

// ---------------------------------------------------------------------------
extern "C" void kernel_launch(void* const* d_in, const int* in_sizes, int n_in,
                              void* d_out, int out_size) {
    const float* z  = (const float*)d_in[0];
    const float* cb = (const float*)d_in[1];
    const int zElems  = in_sizes[0];
    const int cbElems = in_sizes[1];
    const int ntok = zElems / D_DIM;
    const int K    = cbElems / D_DIM;

    float* out     = (float*)d_out;
    float* idx_out = out + (size_t)zElems;
    const int write_idx = (out_size >= zElems + ntok) ? 1 : 0;

    csq_kernel<<<(K + 7) / 8, 256>>>(cb, K);
    prep_cb_kernel<<<(cbElems + 255) / 256, 256>>>(cb, cbElems);

    cudaFuncSetAttribute(vq_kernel,
                         cudaFuncAttributeMaxDynamicSharedMemorySize, SMEM_SZ);
    vq_kernel<<<ntok / BM, THREADS, SMEM_SZ>>>(z, cb, out, idx_out, K, write_idx);
}

// round 14
// speedup vs baseline: 5.5450x; 1.2480x over previous
#include <cuda_runtime.h>
#include <cuda_fp16.h>
#include <cstdint>

#define D_DIM   256
#define BM      64            // tokens per CTA
#define BN      64            // codes per iteration (2 warps x n32)
#define THREADS 256

#define ZROWB   528           // z rows padded: odd 16B stride -> ldsm conflict-free
#define ZSPLIT  (64 * ZROWB)  // 33792 B per z split (h, l)
#define OFF_B   (2 * ZSPLIT)  // 67584
#define BROW    512           // B rows unpadded (bulk-copy contiguous); XOR swizzle instead
#define BSPLIT  (64 * BROW)   // 32768 B per B split per buffer
#define BBUF    (2 * BSPLIT)  // 65536 B per B buffer (h + l)
#define SMEM_SZ (OFF_B + 2 * BBUF)   // 198656 B

__device__ float  g_csq[4096];
__device__ __half g_cbH[4096 * 256];   // pre-swizzled: chunk c at (c&24)|((c&7)^(k&7))
__device__ __half g_cbL[4096 * 256];

// ---------------- helpers -------------------------------------------------
__device__ __forceinline__ uint32_t smem_u32(const void* p) {
    uint32_t a;
    asm("{ .reg .u64 t; cvta.to.shared.u64 t, %1; cvt.u32.u64 %0, t; }"
        : "=r"(a) : "l"(p));
    return a;
}
__device__ __forceinline__ void split2(float v, __half& h, __half& l) {
    h = __float2half_rn(v);
    l = __float2half_rn(v - __half2float(h));   // v-h exact in fp32
}
__device__ __forceinline__ uint32_t packh(__half lo, __half hi) {
    return ((uint32_t)__half_as_ushort(hi) << 16) | __half_as_ushort(lo);
}
__device__ __forceinline__ void ldsm4(uint32_t* r, uint32_t a) {
    asm volatile("ldmatrix.sync.aligned.m8n8.x4.shared.b16 {%0,%1,%2,%3}, [%4];"
                 : "=r"(r[0]), "=r"(r[1]), "=r"(r[2]), "=r"(r[3]) : "r"(a));
}
__device__ __forceinline__ void mma16816(float* c, const uint32_t* a,
                                         uint32_t b0, uint32_t b1) {
    asm volatile(
        "mma.sync.aligned.m16n8k16.row.col.f32.f16.f16.f32 "
        "{%0,%1,%2,%3}, {%4,%5,%6,%7}, {%8,%9}, {%0,%1,%2,%3};"
        : "+f"(c[0]), "+f"(c[1]), "+f"(c[2]), "+f"(c[3])
        : "r"(a[0]), "r"(a[1]), "r"(a[2]), "r"(a[3]), "r"(b0), "r"(b1));
}
__device__ __forceinline__ void bulk_g2s(uint32_t dst, const void* src,
                                         uint32_t bytes, uint32_t mbar) {
    asm volatile(
        "cp.async.bulk.shared::cluster.global.mbarrier::complete_tx::bytes "
        "[%0], [%1], %2, [%3];"
        :: "r"(dst), "l"(src), "r"(bytes), "r"(mbar) : "memory");
}
__device__ __forceinline__ void mbar_init(uint32_t mbar, uint32_t cnt) {
    asm volatile("mbarrier.init.shared.b64 [%0], %1;" :: "r"(mbar), "r"(cnt) : "memory");
}
__device__ __forceinline__ void mbar_expect_tx(uint32_t mbar, uint32_t bytes) {
    asm volatile("mbarrier.arrive.expect_tx.shared.b64 _, [%0], %1;"
                 :: "r"(mbar), "r"(bytes) : "memory");
}
__device__ __forceinline__ void mbar_wait(uint32_t mbar, uint32_t parity) {
    asm volatile(
        "{\n\t.reg .pred P;\n"
        "W%=:\n\t"
        "mbarrier.try_wait.parity.acquire.cta.shared::cta.b64 P, [%0], %1, 0x989680;\n\t"
        "@!P bra W%=;\n\t}"
        :: "r"(mbar), "r"(parity) : "memory");
}

// ---------------- prologue kernels ----------------------------------------
// Write codebook splits pre-swizzled: one 16B chunk per thread.
__global__ void prep_cb_kernel(const float* __restrict__ cb, int nchunk) {
    int i = blockIdx.x * blockDim.x + threadIdx.x;
    if (i >= nchunk) return;
    int k = i >> 5, c = i & 31;                 // row k, logical 16B chunk c
    const float4* s = (const float4*)(cb + (size_t)k * D_DIM + c * 8);
    float4 f0 = __ldg(s), f1 = __ldg(s + 1);
    __half h[8], l[8];
    split2(f0.x, h[0], l[0]); split2(f0.y, h[1], l[1]);
    split2(f0.z, h[2], l[2]); split2(f0.w, h[3], l[3]);
    split2(f1.x, h[4], l[4]); split2(f1.y, h[5], l[5]);
    split2(f1.z, h[6], l[6]); split2(f1.w, h[7], l[7]);
    uint4 H, L;
    H.x = packh(h[0], h[1]); H.y = packh(h[2], h[3]);
    H.z = packh(h[4], h[5]); H.w = packh(h[6], h[7]);
    L.x = packh(l[0], l[1]); L.y = packh(l[2], l[3]);
    L.z = packh(l[4], l[5]); L.w = packh(l[6], l[7]);
    int p = (c & 24) | ((c & 7) ^ (k & 7));     // XOR swizzle baked into gmem
    ((uint4*)g_cbH)[(size_t)k * 32 + p] = H;
    ((uint4*)g_cbL)[(size_t)k * 32 + p] = L;
}
__global__ void csq_kernel(const float* __restrict__ cb, int K) {
    int k = blockIdx.x * (blockDim.x / 32) + (threadIdx.x >> 5);
    int lane = threadIdx.x & 31;
    if (k >= K) return;
    const float* row = cb + (size_t)k * D_DIM;
    float s = 0.f;
    #pragma unroll
    for (int d = lane; d < D_DIM; d += 32) {
        float v = row[d];
        s = fmaf(v, v, s);
    }
    #pragma unroll
    for (int o = 16; o; o >>= 1) s += __shfl_xor_sync(0xffffffffu, s, o);
    if (lane == 0) g_csq[k] = s;
}

// ---------------- main kernel ---------------------------------------------
// 8 warps: wm = wid>>1 (token rows 16*wm..), wn = wid&1 (codes 32*wn..).
// fp16 2-split, 3 products (hh, hl, lh) -> fp32-grade distances.
// B fed by cp.async.bulk (1 instr / 32KB split) + mbarrier double buffer.
__global__ __launch_bounds__(THREADS, 1)
void vq_kernel(const float* __restrict__ z, const float* __restrict__ cb,
               float* __restrict__ zq, float* __restrict__ idx_out,
               int K, int write_idx) {
    extern __shared__ char smem[];
    __shared__ uint64_t mbars[2];
    const uint32_t sbase = smem_u32(smem);
    const uint32_t mb0 = smem_u32(&mbars[0]);
    const uint32_t mb1 = smem_u32(&mbars[1]);

    const int tid  = threadIdx.x;
    const int lane = tid & 31;
    const int wid  = tid >> 5;
    const int wm   = wid >> 1;
    const int wn   = wid & 1;
    const long m0  = (long)blockIdx.x * BM;
    const int NT   = K / BN;               // 16

    if (tid == 0) { mbar_init(mb0, 1); mbar_init(mb1, 1); }

    // ---- stage z splits into smem (row = tid>>2, 64 dims per thread) ----
    {
        int row = tid >> 2, seg = tid & 3;
        const float4* zr = (const float4*)(z + (m0 + row) * D_DIM) + seg * 16;
        char* zb = smem + row * ZROWB + seg * 128;
        #pragma unroll
        for (int q = 0; q < 16; q++) {
            float4 f = __ldg(zr + q);
            __half h0, l0, h1, l1, h2, l2, h3, l3;
            split2(f.x, h0, l0); split2(f.y, h1, l1);
            split2(f.z, h2, l2); split2(f.w, h3, l3);
            *(uint32_t*)(zb + 0 * ZSPLIT + q * 8)     = packh(h0, h1);
            *(uint32_t*)(zb + 0 * ZSPLIT + q * 8 + 4) = packh(h2, h3);
            *(uint32_t*)(zb + 1 * ZSPLIT + q * 8)     = packh(l0, l1);
            *(uint32_t*)(zb + 1 * ZSPLIT + q * 8 + 4) = packh(l2, l3);
        }
    }
    __syncthreads();   // mbar init + z smem visible to all

    // ---- kick off B tiles 0 and 1 (one bulk op per 32KB split) ----
    if (tid == 0) {
        mbar_expect_tx(mb0, BBUF);
        bulk_g2s(sbase + OFF_B + 0 * BBUF + 0 * BSPLIT, (const char*)g_cbH, BSPLIT, mb0);
        bulk_g2s(sbase + OFF_B + 0 * BBUF + 1 * BSPLIT, (const char*)g_cbL, BSPLIT, mb0);
        mbar_expect_tx(mb1, BBUF);
        bulk_g2s(sbase + OFF_B + 1 * BBUF + 0 * BSPLIT, (const char*)g_cbH + BSPLIT, BSPLIT, mb1);
        bulk_g2s(sbase + OFF_B + 1 * BBUF + 1 * BSPLIT, (const char*)g_cbL + BSPLIT, BSPLIT, mb1);
    }

    // ldmatrix addresses
    const int lr = lane & 15, lh = lane >> 4;
    const int r7 = lr & 7;
    const uint32_t aAddr = sbase + (uint32_t)(wm * 16 + lr) * ZROWB + lh * 16;
    const uint32_t bRow0 = sbase + OFF_B + (uint32_t)(wn * 32 + lr) * BROW;

    float bD[2] = {3.4e38f, 3.4e38f};
    int   bI[2] = {0, 0};

    for (int t = 0; t < NT; ++t) {
        mbar_wait((t & 1) ? mb1 : mb0, (t >> 1) & 1);

        const uint32_t bBase = bRow0 + (uint32_t)(t & 1) * BBUF;

        float acc[4][4];
        #pragma unroll
        for (int g = 0; g < 4; g++)
            #pragma unroll
            for (int r = 0; r < 4; r++) acc[g][r] = 0.f;

        #pragma unroll
        for (int kk = 0; kk < 16; ++kk) {
            uint32_t aH[4], aL[4];
            ldsm4(aH, aAddr + 0 * ZSPLIT + kk * 32);
            ldsm4(aL, aAddr + 1 * ZSPLIT + kk * 32);
            // B chunk swizzle: logical chunk c = 2kk+lh;
            // phys*16 = ((2kk&24)<<4) + (((2kk&7)+lh)^r7)<<4
            const uint32_t hi16 = (uint32_t)(((2 * kk) & 24) << 4);
            const uint32_t sw16 = ((((uint32_t)((2 * kk) & 7) + lh) ^ r7) << 4);
            #pragma unroll
            for (int h = 0; h < 2; h++) {          // 16-code halves of n32
                uint32_t bH[4], bL[4];
                uint32_t ba = bBase + (uint32_t)(h * 16) * BROW + hi16 + sw16;
                ldsm4(bH, ba + 0 * BSPLIT);
                ldsm4(bL, ba + 1 * BSPLIT);
                #pragma unroll
                for (int s = 0; s < 2; s++) {      // n8 within 16 codes
                    float* a = acc[h * 2 + s];
                    mma16816(a, aH, bH[s], bH[s + 2]);   // hh
                    mma16816(a, aH, bL[s], bL[s + 2]);   // hl
                    mma16816(a, aL, bH[s], bH[s + 2]);   // lh
                }
            }
        }

        // per-tile argmin: dist = ||c||^2 - 2 z.c  (||z||^2 row-constant)
        const int n0 = t * BN;
        #pragma unroll
        for (int g = 0; g < 4; g++) {
            int colb = n0 + wn * 32 + (g >> 1) * 16 + (g & 1) * 8 + 2 * (lane & 3);
            float q0 = g_csq[colb], q1 = g_csq[colb + 1];
            float d0 = fmaf(-2.f, acc[g][0], q0);
            float d1 = fmaf(-2.f, acc[g][1], q1);
            float d2 = fmaf(-2.f, acc[g][2], q0);
            float d3 = fmaf(-2.f, acc[g][3], q1);
            if (d0 < bD[0]) { bD[0] = d0; bI[0] = colb; }
            if (d1 < bD[0]) { bD[0] = d1; bI[0] = colb + 1; }
            if (d2 < bD[1]) { bD[1] = d2; bI[1] = colb; }
            if (d3 < bD[1]) { bD[1] = d3; bI[1] = colb + 1; }
        }

        __syncthreads();   // all warps done with buffer t&1

        // refill this buffer with tile t+2
        if (t + 2 < NT && tid == 0) {
            uint32_t mb = (t & 1) ? mb1 : mb0;
            uint32_t dst = sbase + OFF_B + (uint32_t)(t & 1) * BBUF;
            size_t goff = (size_t)(t + 2) * BSPLIT;
            mbar_expect_tx(mb, BBUF);
            bulk_g2s(dst + 0 * BSPLIT, (const char*)g_cbH + goff, BSPLIT, mb);
            bulk_g2s(dst + 1 * BSPLIT, (const char*)g_cbL + goff, BSPLIT, mb);
        }
    }

    // ---- cross-thread argmin (8 slots per token row), aliasing z smem ----
    float* redD   = (float*)smem;            // [64][8]
    int*   redI   = (int*)(smem + 2048);     // [64][8]
    int*   rowIdx = (int*)(smem + 4096);     // [64]
    __syncthreads();
    {
        int g = lane >> 2;
        int slot = wn * 4 + (lane & 3);
        int r0 = wm * 16 + g;
        redD[r0 * 8 + slot] = bD[0];        redI[r0 * 8 + slot] = bI[0];
        redD[(r0 + 8) * 8 + slot] = bD[1];  redI[(r0 + 8) * 8 + slot] = bI[1];
    }
    __syncthreads();
    if (tid < BM) {
        float bd = redD[tid * 8];
        int   bi = redI[tid * 8];
        #pragma unroll
        for (int s = 1; s < 8; s++) {
            float d = redD[tid * 8 + s];
            int  ii = redI[tid * 8 + s];
            if (d < bd || (d == bd && ii < bi)) { bd = d; bi = ii; }
        }
        rowIdx[tid] = bi;
        if (write_idx) idx_out[m0 + tid] = (float)bi;
    }
    __syncthreads();

    // ---- gather z_q = codebook[idx] from exact fp32 codebook ----
    float4* zqdst = (float4*)(zq + m0 * D_DIM);
    #pragma unroll 4
    for (int f = tid; f < BM * (D_DIM / 4); f += THREADS) {
        float4 v = __ldg((const float4*)(cb + (size_t)rowIdx[f >> 6] * D_DIM + (f & 63) * 4));
        zqdst[f] = v;
    }
}

// ---------------------------------------------------------------------------
extern "C" void kernel_launch(void* const* d_in, const int* in_sizes, int n_in,
                              void* d_out, int out_size) {
    const float* z  = (const float*)d_in[0];
    const float* cb = (const float*)d_in[1];
    const int zElems  = in_sizes[0];
    const int cbElems = in_sizes[1];
    const int ntok = zElems / D_DIM;
    const int K    = cbElems / D_DIM;

    float* out     = (float*)d_out;
    float* idx_out = out + (size_t)zElems;
    const int write_idx = (out_size >= zElems + ntok) ? 1 : 0;

    csq_kernel<<<(K + 7) / 8, 256>>>(cb, K);
    prep_cb_kernel<<<(K * 32 + 255) / 256, 256>>>(cb, K * 32);

    cudaFuncSetAttribute(vq_kernel,
                         cudaFuncAttributeMaxDynamicSharedMemorySize, SMEM_SZ);
    vq_kernel<<<ntok / BM, THREADS, SMEM_SZ>>>(z, cb, out, idx_out, K, write_idx);
}